// round 12
// baseline (speedup 1.0000x reference)
#include <cuda_runtime.h>

#define BB    512
#define SEQL  96
#define PREDL 48
#define TOTL  144
#define CIN   7
#define DM    128
#define G3    384
#define KSZ   5
#define PADL  2
#define NWIN  48
#define WCONV (KSZ*DM*DM)   // 81920

// ---------------- device scratch ----------------
__device__ float g_temb[BB * TOTL * DM];
__device__ float g_xcat[BB * TOTL * CIN];
__device__ float g_emb [BB * TOTL * DM];
__device__ float g_c1  [BB * TOTL * DM];
__device__ float g_c2  [BB * TOTL * DM];
__device__ float g_c3  [BB * TOTL * DM];
__device__ float g_c1p [BB * TOTL * DM];     // pre-activation (no bias/relu)
__device__ float g_c2p [BB * TOTL * DM];
__device__ float g_c3p [BB * TOTL * DM];
__device__ float g_gx  [BB * TOTL * G3];
__device__ float g_lbgx[(size_t)PREDL * BB * 6 * G3];
__device__ float g_lb1 [BB * NWIN * 2 * DM];
__device__ float g_lb2 [BB * NWIN * 4 * DM];
__device__ float g_lb3 [BB * NWIN * 6 * DM];
__device__ float g_wc  [3 * WCONV];          // [sel][tap*128+ic][o]
__device__ float g_wvt [CIN * DM];
__device__ float g_wit [DM * G3];            // Wi^T [d][g]

__device__ __forceinline__ float* sel_buf(int s) {
    switch (s) {
        case 0: return g_emb; case 1: return g_c1; case 2: return g_c2;
        case 3: return g_c3;  default: return g_gx;
    }
}
__device__ __forceinline__ const float* sel_w(int s) {
    return (s < 3) ? (g_wc + s * WCONV) : g_wit;
}

__device__ __forceinline__ void ffma2(unsigned long long& acc,
                                      unsigned long long a, unsigned long long w) {
    asm("fma.rn.f32x2 %0, %1, %2, %0;" : "+l"(acc) : "l"(a), "l"(w));
}
__device__ __forceinline__ float sum2(unsigned long long v) {
    float2 f = *reinterpret_cast<float2*>(&v);
    return f.x + f.y;
}

// ---------------- prep ----------------
__global__ void pack_kernel(const float* __restrict__ w1, const float* __restrict__ w2,
                            const float* __restrict__ w3, const float* __restrict__ wval,
                            const float* __restrict__ wi) {
    int idx = blockIdx.x * 256 + threadIdx.x;
    if (idx < WCONV) {
        int r = idx / DM, o = idx - r * DM;
        int k = r / DM,  i = r - k * DM;
        int s = (o * DM + i) * KSZ + k;
        g_wc[idx]             = w1[s];
        g_wc[WCONV + idx]     = w2[s];
        g_wc[2 * WCONV + idx] = w3[s];
    }
    if (idx < DM * G3) {
        int d = idx / G3, g = idx - d * G3;
        g_wit[idx] = wi[g * DM + d];
    }
    if (idx < CIN * DM) {
        int c = idx / DM, d = idx - c * DM;
        g_wvt[idx] = wval[d * CIN + c];
    }
}

__global__ void temb_kernel(const int* __restrict__ ymark,
                            const float* __restrict__ hour, const float* __restrict__ wk,
                            const float* __restrict__ day,  const float* __restrict__ mon) {
    int bl = blockIdx.x, d = threadIdx.x;
    const int* y = ymark + bl * 4;
    g_temb[bl * DM + d] = hour[y[0] * DM + d] + wk[y[1] * DM + d]
                        + day [y[2] * DM + d] + mon[y[3] * DM + d];
}

__global__ void initx_kernel(const float* __restrict__ xenc) {
    int idx = blockIdx.x * 256 + threadIdx.x;
    if (idx >= BB * TOTL * CIN) return;
    int c = idx % CIN;
    int t = (idx / CIN) % TOTL;
    int b = idx / (CIN * TOTL);
    g_xcat[idx] = (t < SEQL) ? xenc[(b * SEQL + t) * CIN + c] : 0.f;
}

__global__ void embed_kernel(const float* __restrict__ bval) {
    int bl = blockIdx.x;                       // b*SEQL + p
    int b = bl / SEQL, p = bl - b * SEQL;
    int d = threadIdx.x;
    __shared__ float xs[CIN];
    if (d < CIN) xs[d] = g_xcat[(b * TOTL + p) * CIN + d];
    __syncthreads();
    float acc = bval[d] + g_temb[(b * TOTL + p) * DM + d];
#pragma unroll
    for (int c = 0; c < CIN; c++) acc = fmaf(xs[c], g_wvt[c * DM + d], acc);
    g_emb[(b * TOTL + p) * DM + d] = acc;
}

// ---------------- tiled GEMM for the initial full pass ----------------
__global__ __launch_bounds__(256) void convgemm(
    int ssel, int srcBS, int pbase, int qlo, int qhi,
    int wsel, int Nw, const float* __restrict__ bias,
    int dsel, int dstBS, int dstPS, int dstPB,
    int npos, int KC, int relu)
{
    const float* __restrict__ src = sel_buf(ssel);
    const float* __restrict__ w   = sel_w(wsel);
    float*       __restrict__ dst = sel_buf(dsel);
    float* prebuf = (dsel == 1) ? g_c1p : (dsel == 2) ? g_c2p : (dsel == 3) ? g_c3p : nullptr;

    __shared__ float As[16][33];
    __shared__ float Bs[16][DM];

    int tid = threadIdx.x;
    int tx = tid & 15, ty = tid >> 4;
    int ncol0 = blockIdx.y * DM;

    int R0 = blockIdx.x * 32 + ty;
    int R1 = R0 + 16;
    int b0 = R0 / npos, p0 = R0 - b0 * npos;
    int b1 = R1 / npos, p1 = R1 - b1 * npos;
    const float* s0 = src + (size_t)b0 * srcBS;
    const float* s1 = src + (size_t)b1 * srcBS;
    int pr0 = pbase + p0 - PADL;
    int pr1 = pbase + p1 - PADL;

    float acc[2][8];
#pragma unroll
    for (int m = 0; m < 2; m++)
#pragma unroll
        for (int n = 0; n < 8; n++) acc[m][n] = 0.f;

    for (int kc = 0; kc < KC; kc++) {
        int tap = kc >> 3;
        int icb = (kc & 7) << 4;
        int q0 = pr0 + tap, q1 = pr1 + tap;
        float v0 = (q0 >= qlo && q0 <= qhi) ? s0[(size_t)q0 * DM + icb + tx] : 0.f;
        float v1 = (q1 >= qlo && q1 <= qhi) ? s1[(size_t)q1 * DM + icb + tx] : 0.f;
        As[tx][ty]      = v0;
        As[tx][ty + 16] = v1;
#pragma unroll
        for (int qq = 0; qq < 8; qq++) {
            int e = tid + 256 * qq;
            int kk = e >> 7, o = e & 127;
            Bs[kk][o] = w[(size_t)(kc * 16 + kk) * Nw + ncol0 + o];
        }
        __syncthreads();
#pragma unroll
        for (int rr = 0; rr < 16; rr++) {
            float a0 = As[rr][ty], a1 = As[rr][ty + 16];
            float bv[8];
#pragma unroll
            for (int n = 0; n < 8; n++) bv[n] = Bs[rr][tx + 16 * n];
#pragma unroll
            for (int n = 0; n < 8; n++) {
                acc[0][n] = fmaf(a0, bv[n], acc[0][n]);
                acc[1][n] = fmaf(a1, bv[n], acc[1][n]);
            }
        }
        __syncthreads();
    }
#pragma unroll
    for (int m = 0; m < 2; m++) {
        int b = m ? b1 : b0;
        int pi = m ? p1 : p0;
        size_t base = (size_t)b * dstBS + (size_t)(dstPB + pi) * dstPS + ncol0;
#pragma unroll
        for (int n = 0; n < 8; n++) {
            int o = tx + 16 * n;
            float pre = acc[m][n];                 // pre-act (no bias) for delta scheme
            float v = pre + bias[ncol0 + o];
            if (prebuf) prebuf[base + o] = pre;
            dst[base + o] = relu ? fmaxf(v, 0.f) : v;
        }
    }
}

// ---------------- left-boundary cascades as 4 chip-wide GEMMs ----------------
template<int ST>
__device__ __forceinline__ float lb_fetch(int b, int win, int a, int ic) {
    if (ST == 0) return (a >= 0) ? g_emb[((size_t)b * TOTL + win + a) * DM + ic] : 0.f;
    if (ST == 1) {
        if (a < 0) return 0.f;
        return (a < 2) ? g_lb1[(((size_t)b * NWIN + win) * 2 + a) * DM + ic]
                       : g_c1[((size_t)b * TOTL + win + a) * DM + ic];
    }
    if (a < 0) return 0.f;
    return (a < 4) ? g_lb2[(((size_t)b * NWIN + win) * 4 + a) * DM + ic]
                   : g_c2[((size_t)b * TOTL + win + a) * DM + ic];
}

template<int ST>
__global__ __launch_bounds__(256) void lbgemm(const float* __restrict__ bias) {
    constexpr int NPOS = (ST == 0) ? 2 : (ST == 1) ? 4 : 6;
    constexpr int KC   = (ST == 3) ? 8 : 40;
    constexpr int NW   = (ST == 3) ? G3 : DM;

    __shared__ float As[16][33];
    __shared__ float Bs[16][DM];

    int tid = threadIdx.x;
    int tx = tid & 15, ty = tid >> 4;
    int ncol0 = blockIdx.y * DM;
    const float* __restrict__ w = (ST == 3) ? g_wit : (g_wc + ST * WCONV);

    int R0 = blockIdx.x * 32 + ty, R1 = R0 + 16;
    int p0 = R0 % NPOS, wb0 = R0 / NPOS, win0 = wb0 % NWIN, b0 = wb0 / NWIN;
    int p1 = R1 % NPOS, wb1 = R1 / NPOS, win1 = wb1 % NWIN, b1 = wb1 / NWIN;

    float acc[2][8];
#pragma unroll
    for (int m = 0; m < 2; m++)
#pragma unroll
        for (int n = 0; n < 8; n++) acc[m][n] = 0.f;

    for (int kc = 0; kc < KC; kc++) {
        int tap = kc >> 3;
        int ic  = ((kc & 7) << 4) + tx;
        float v0, v1;
        if (ST == 3) {
            v0 = g_lb3[(((size_t)b0 * NWIN + win0) * 6 + p0) * DM + ic];
            v1 = g_lb3[(((size_t)b1 * NWIN + win1) * 6 + p1) * DM + ic];
        } else {
            v0 = lb_fetch<ST>(b0, win0, p0 + tap - PADL, ic);
            v1 = lb_fetch<ST>(b1, win1, p1 + tap - PADL, ic);
        }
        As[tx][ty]      = v0;
        As[tx][ty + 16] = v1;
#pragma unroll
        for (int qq = 0; qq < 8; qq++) {
            int e = tid + 256 * qq;
            int kk = e >> 7, o = e & 127;
            Bs[kk][o] = w[(size_t)(kc * 16 + kk) * NW + ncol0 + o];
        }
        __syncthreads();
#pragma unroll
        for (int rr = 0; rr < 16; rr++) {
            float a0 = As[rr][ty], a1 = As[rr][ty + 16];
            float bv[8];
#pragma unroll
            for (int n = 0; n < 8; n++) bv[n] = Bs[rr][tx + 16 * n];
#pragma unroll
            for (int n = 0; n < 8; n++) {
                acc[0][n] = fmaf(a0, bv[n], acc[0][n]);
                acc[1][n] = fmaf(a1, bv[n], acc[1][n]);
            }
        }
        __syncthreads();
    }
#pragma unroll
    for (int m = 0; m < 2; m++) {
        int b = m ? b1 : b0, win = m ? win1 : win0, p = m ? p1 : p0;
#pragma unroll
        for (int n = 0; n < 8; n++) {
            int o = tx + 16 * n;
            float v = acc[m][n] + bias[ncol0 + o];
            if (ST == 0) g_lb1[(((size_t)b * NWIN + win) * 2 + p) * DM + o] = fmaxf(v, 0.f);
            if (ST == 1) g_lb2[(((size_t)b * NWIN + win) * 4 + p) * DM + o] = fmaxf(v, 0.f);
            if (ST == 2) g_lb3[(((size_t)b * NWIN + win) * 6 + p) * DM + o] = fmaxf(v, 0.f);
            if (ST == 3) g_lbgx[(((size_t)win * BB + b) * 6 + p) * G3 + ncol0 + o] = v;
        }
    }
}

// ---------------- persistent loop: 48 steps, delta-prologue + GRU ----------------
__global__ __launch_bounds__(384, 1) void loop_kernel(
        const float* __restrict__ Wh,  const float* __restrict__ bh,
        const float* __restrict__ fcw, const float* __restrict__ fcb,
        const float* __restrict__ bval,
        const float* __restrict__ c1b, const float* __restrict__ c2b,
        const float* __restrict__ c3b, const float* __restrict__ gbi,
        float* __restrict__ dout) {
    int tid = threadIdx.x;
    int b0  = blockIdx.x * 4;

    __shared__ __align__(16) float h_s[4][DM];
    __shared__ float S1[4][G3];
    __shared__ float S2[4][DM];
    __shared__ float sPred[4][CIN];
    __shared__ float sEmb[4][DM];
    __shared__ float sD1[4 * 3 * DM];    // delta c1, pos F-2+k
    __shared__ float sD2[4 * 5 * DM];    // delta c2, pos F-4+m

    for (int i = 0; i < PREDL; i++) {
        if (i > 0) {
            __syncthreads();   // sPred(i-1) visible, smem free
            const int F = SEQL - 1 + i;

            // ---- Stage E: embedding at frontier F ----
            for (int e = tid; e < 4 * DM; e += 384) {
                int r = e >> 7, d = e & 127;
                int b = b0 + r;
                float a = bval[d] + g_temb[((size_t)b * TOTL + F) * DM + d];
#pragma unroll
                for (int c = 0; c < CIN; c++) a = fmaf(sPred[r][c], g_wvt[c * DM + d], a);
                sEmb[r][d] = a;
                g_emb[((size_t)b * TOTL + F) * DM + d] = a;
            }
            __syncthreads();

            // ---- Stage C1: 3 positions (F-2, F-1 update; F fresh) ----
            for (int e = tid; e < 3 * 512; e += 384) {
                int k = e >> 9, r = (e >> 7) & 3, o = e & 127;
                int p = F - 2 + k;
                size_t gi = ((size_t)(b0 + r) * TOTL + p) * DM + o;
                float pre;
                if (k < 2) {
                    int tap = 4 - k;
                    const float* wp = g_wc + (size_t)(tap * DM) * DM + o;
                    const float* xe = sEmb[r];
                    float a0 = 0.f, a1 = 0.f, a2 = 0.f, a3 = 0.f;
                    for (int ic = 0; ic < DM; ic += 4) {
                        a0 = fmaf(wp[(ic + 0) * DM], xe[ic + 0], a0);
                        a1 = fmaf(wp[(ic + 1) * DM], xe[ic + 1], a1);
                        a2 = fmaf(wp[(ic + 2) * DM], xe[ic + 2], a2);
                        a3 = fmaf(wp[(ic + 3) * DM], xe[ic + 3], a3);
                    }
                    pre = g_c1p[gi] + ((a0 + a1) + (a2 + a3));
                } else {
                    const float* w0 = g_wc + o;                        // tap 0
                    const float* w1 = g_wc + (size_t)DM * DM + o;      // tap 1
                    const float* w2 = g_wc + (size_t)2 * DM * DM + o;  // tap 2
                    const float* x0 = g_emb + ((size_t)(b0 + r) * TOTL + F - 2) * DM;
                    const float* x1 = g_emb + ((size_t)(b0 + r) * TOTL + F - 1) * DM;
                    const float* x2 = sEmb[r];
                    float a0 = 0.f, a1 = 0.f, a2 = 0.f, a3 = 0.f, a4 = 0.f, a5 = 0.f;
                    for (int ic = 0; ic < DM; ic += 2) {
                        a0 = fmaf(w0[ic * DM], x0[ic], a0);
                        a1 = fmaf(w1[ic * DM], x1[ic], a1);
                        a2 = fmaf(w2[ic * DM], x2[ic], a2);
                        a3 = fmaf(w0[(ic + 1) * DM], x0[ic + 1], a3);
                        a4 = fmaf(w1[(ic + 1) * DM], x1[ic + 1], a4);
                        a5 = fmaf(w2[(ic + 1) * DM], x2[ic + 1], a5);
                    }
                    pre = ((a0 + a3) + (a1 + a4)) + (a2 + a5);
                }
                float nw = fmaxf(pre + c1b[o], 0.f);
                float old = (k < 2) ? g_c1[gi] : 0.f;   // p=F never existed before
                sD1[(r * 3 + k) * DM + o] = nw - old;
                g_c1[gi] = nw;
                g_c1p[gi] = pre;
            }
            __syncthreads();

            // ---- Stage C2: 5 positions F-4..F via delta(c1); fresh row uses FULL c1 ----
            for (int e = tid; e < 5 * 512; e += 384) {
                int m = e >> 9, r = (e >> 7) & 3, o = e & 127;
                int p = F - 4 + m;
                size_t gi = ((size_t)(b0 + r) * TOTL + p) * DM + o;
                float pre = (m == 4) ? 0.f : g_c2p[gi];
                int klo = (m > 3) ? m - 4 : 0;
                int khi = (m < 2) ? m : 2;
                float a0 = 0.f, a1 = 0.f, a2 = 0.f, a3 = 0.f;
                for (int k = klo; k <= khi; k++) {
                    int tap = k - m + 4;
                    const float* wp = g_wc + WCONV + (size_t)(tap * DM) * DM + o;
                    // fresh position (m==4): old pre is 0, so inputs need FULL new
                    // c1 values (just written above, block-visible after barrier),
                    // not deltas. Updated positions use deltas.
                    const float* dp = (m == 4)
                        ? (g_c1 + ((size_t)(b0 + r) * TOTL + F - 2 + k) * DM)
                        : (sD1 + (r * 3 + k) * DM);
                    for (int ic = 0; ic < DM; ic += 4) {
                        a0 = fmaf(wp[(ic + 0) * DM], dp[ic + 0], a0);
                        a1 = fmaf(wp[(ic + 1) * DM], dp[ic + 1], a1);
                        a2 = fmaf(wp[(ic + 2) * DM], dp[ic + 2], a2);
                        a3 = fmaf(wp[(ic + 3) * DM], dp[ic + 3], a3);
                    }
                }
                pre += (a0 + a1) + (a2 + a3);
                float nw = fmaxf(pre + c2b[o], 0.f);
                sD2[(r * 5 + m) * DM + o] = (m < 4) ? nw - g_c2[gi] : nw;
                g_c2[gi] = nw;
                g_c2p[gi] = pre;
            }
            __syncthreads();

            // ---- Stage C3: 7 positions F-6..F via delta(c2); fresh row uses FULL c2 ----
            for (int e = tid; e < 7 * 512; e += 384) {
                int m = e >> 9, r = (e >> 7) & 3, o = e & 127;
                int p = F - 6 + m;
                size_t gi = ((size_t)(b0 + r) * TOTL + p) * DM + o;
                float pre = (m == 6) ? 0.f : g_c3p[gi];
                int jlo = m - 4; if (jlo < 0) jlo = 0;
                int jhi = (m < 4) ? m : 4;
                float a0 = 0.f, a1 = 0.f, a2 = 0.f, a3 = 0.f;
                for (int j = jlo; j <= jhi; j++) {
                    int tap = j - m + 4;
                    const float* wp = g_wc + 2 * WCONV + (size_t)(tap * DM) * DM + o;
                    const float* dp = (m == 6)
                        ? (g_c2 + ((size_t)(b0 + r) * TOTL + F - 4 + j) * DM)
                        : (sD2 + (r * 5 + j) * DM);
                    for (int ic = 0; ic < DM; ic += 4) {
                        a0 = fmaf(wp[(ic + 0) * DM], dp[ic + 0], a0);
                        a1 = fmaf(wp[(ic + 1) * DM], dp[ic + 1], a1);
                        a2 = fmaf(wp[(ic + 2) * DM], dp[ic + 2], a2);
                        a3 = fmaf(wp[(ic + 3) * DM], dp[ic + 3], a3);
                    }
                }
                pre += (a0 + a1) + (a2 + a3);
                float nw = fmaxf(pre + c3b[o], 0.f);
                g_c3[gi] = nw;
                g_c3p[gi] = pre;
            }
            __syncthreads();

            // ---- Stage GX: gx at F-6..F from fresh c3 (global, CTA-visible) ----
            {
                int rq = tid / 96, cq = tid - rq * 96;
                float acc[7][4];
#pragma unroll
                for (int p = 0; p < 7; p++)
#pragma unroll
                    for (int c = 0; c < 4; c++) acc[p][c] = 0.f;
                const float4* wv = reinterpret_cast<const float4*>(g_wit) + cq;
                const float* xb = g_c3 + ((size_t)(b0 + rq) * TOTL + F - 6) * DM;
                for (int k = 0; k < DM; k += 4) {
                    float4 x4[7];
#pragma unroll
                    for (int p = 0; p < 7; p++)
                        x4[p] = *reinterpret_cast<const float4*>(xb + p * DM + k);
#pragma unroll
                    for (int kk = 0; kk < 4; kk++) {
                        float4 w = wv[(size_t)(k + kk) * 96];
#pragma unroll
                        for (int p = 0; p < 7; p++) {
                            float x = (kk == 0) ? x4[p].x : (kk == 1) ? x4[p].y
                                     : (kk == 2) ? x4[p].z : x4[p].w;
                            acc[p][0] = fmaf(w.x, x, acc[p][0]);
                            acc[p][1] = fmaf(w.y, x, acc[p][1]);
                            acc[p][2] = fmaf(w.z, x, acc[p][2]);
                            acc[p][3] = fmaf(w.w, x, acc[p][3]);
                        }
                    }
                }
                float4 bo = reinterpret_cast<const float4*>(gbi)[cq];
#pragma unroll
                for (int p = 0; p < 7; p++) {
                    float4 v;
                    v.x = acc[p][0] + bo.x; v.y = acc[p][1] + bo.y;
                    v.z = acc[p][2] + bo.z; v.w = acc[p][3] + bo.w;
                    *reinterpret_cast<float4*>(
                        g_gx + ((size_t)(b0 + rq) * TOTL + F - 6 + p) * G3 + cq * 4) = v;
                }
            }
            __syncthreads();
        }

        // ---- GRU t-loop ----
        int j = tid;
        ulonglong2 wr[32];
        {
            const ulonglong2* p = reinterpret_cast<const ulonglong2*>(Wh + (size_t)j * DM);
#pragma unroll
            for (int q = 0; q < 32; q++) wr[q] = p[q];
        }
        float bhj = bh[j];

        for (int e = j; e < 4 * DM; e += 384) (&h_s[0][0])[e] = 0.f;
        __syncthreads();

        // preload gx for t = 0
        float gxv[4];
#pragma unroll
        for (int r = 0; r < 4; r++)
            gxv[r] = g_lbgx[(((size_t)i * BB + b0 + r) * 6 + 0) * G3 + j];

        for (int t = 0; t < SEQL; t++) {
            // prefetch next-t gx early (covered by the FMA chain below)
            float gxn[4] = {0.f, 0.f, 0.f, 0.f};
            if (t + 1 < SEQL) {
#pragma unroll
                for (int r = 0; r < 4; r++) {
                    int b = b0 + r;
                    gxn[r] = (t + 1 < 6)
                        ? g_lbgx[(((size_t)i * BB + b) * 6 + (t + 1)) * G3 + j]
                        : g_gx[((size_t)b * TOTL + i + t + 1) * G3 + j];
                }
            }
            unsigned long long c0 = 0, c1 = 0, c2 = 0, c3 = 0;
            const ulonglong2* h0 = reinterpret_cast<const ulonglong2*>(h_s[0]);
            const ulonglong2* h1 = reinterpret_cast<const ulonglong2*>(h_s[1]);
            const ulonglong2* h2 = reinterpret_cast<const ulonglong2*>(h_s[2]);
            const ulonglong2* h3 = reinterpret_cast<const ulonglong2*>(h_s[3]);
#pragma unroll
            for (int q = 0; q < 32; q++) {
                ulonglong2 w  = wr[q];
                ulonglong2 x0 = h0[q], x1 = h1[q], x2 = h2[q], x3 = h3[q];
                ffma2(c0, x0.x, w.x); ffma2(c0, x0.y, w.y);
                ffma2(c1, x1.x, w.x); ffma2(c1, x1.y, w.y);
                ffma2(c2, x2.x, w.x); ffma2(c2, x2.y, w.y);
                ffma2(c3, x3.x, w.x); ffma2(c3, x3.y, w.y);
            }
            float accs[4] = {sum2(c0), sum2(c1), sum2(c2), sum2(c3)};
#pragma unroll
            for (int r = 0; r < 4; r++) {
                float gh = accs[r] + bhj;
                if (j < 2 * DM) S1[r][j] = gxv[r] + gh;
                else            { S1[r][j] = gh; S2[r][j - 2 * DM] = gxv[r]; }
            }
            __syncthreads();
            for (int e = j; e < 4 * DM; e += 384) {
                int r = e >> 7, d = e & 127;
                float rg = __fdividef(1.f, 1.f + __expf(-S1[r][d]));
                float zg = __fdividef(1.f, 1.f + __expf(-S1[r][DM + d]));
                float na = S2[r][d] + rg * S1[r][2 * DM + d];
                float ng = 1.f - __fdividef(2.f, __expf(2.f * na) + 1.f);
                h_s[r][d] = (1.f - zg) * ng + zg * h_s[r][d];
            }
            __syncthreads();
#pragma unroll
            for (int r = 0; r < 4; r++) gxv[r] = gxn[r];
        }

        if (j < 4 * CIN) {
            int r = j / CIN, c = j - r * CIN;
            float acc = fcb[c];
            for (int d = 0; d < DM; d++) acc = fmaf(h_s[r][d], fcw[c * DM + d], acc);
            sPred[r][c] = acc;
            dout[((size_t)(b0 + r) * PREDL + i) * CIN + c] = acc;
        }
    }
}

// ---------------- launcher ----------------
extern "C" void kernel_launch(void* const* d_in, const int* in_sizes, int n_in,
                              void* d_out, int out_size) {
    (void)in_sizes; (void)n_in; (void)out_size;
    const float* x_enc  = (const float*)d_in[0];
    const int*   y_mark = (const int*)  d_in[2];
    const float* hour_e = (const float*)d_in[3];
    const float* wk_e   = (const float*)d_in[4];
    const float* day_e  = (const float*)d_in[5];
    const float* mon_e  = (const float*)d_in[6];
    const float* W_val  = (const float*)d_in[7];
    const float* b_val  = (const float*)d_in[8];
    const float* c1w    = (const float*)d_in[9];
    const float* c1b    = (const float*)d_in[10];
    const float* c2w    = (const float*)d_in[11];
    const float* c2b    = (const float*)d_in[12];
    const float* c3w    = (const float*)d_in[13];
    const float* c3b    = (const float*)d_in[14];
    const float* gWi    = (const float*)d_in[15];
    const float* gWh    = (const float*)d_in[16];
    const float* gbi    = (const float*)d_in[17];
    const float* gbh    = (const float*)d_in[18];
    const float* fcw    = (const float*)d_in[19];
    const float* fcb    = (const float*)d_in[20];
    float* out = (float*)d_out;

    const int SBS = TOTL * DM;
    const int GBS = TOTL * G3;

    pack_kernel<<<(WCONV + 255) / 256, 256>>>(c1w, c2w, c3w, W_val, gWi);
    temb_kernel<<<BB * TOTL, DM>>>(y_mark, hour_e, wk_e, day_e, mon_e);
    initx_kernel<<<(BB * TOTL * CIN + 255) / 256, 256>>>(x_enc);
    embed_kernel<<<BB * SEQL, DM>>>(b_val);

    // initial full pass over positions [0,95] (writes pre-activation arrays too)
    convgemm<<<1536, 256>>>(0, SBS, 0, 0, 95, 0, DM, c1b, 1, SBS, DM, 0, 96, 40, 1);
    convgemm<<<1536, 256>>>(1, SBS, 0, 0, 95, 1, DM, c2b, 2, SBS, DM, 0, 96, 40, 1);
    convgemm<<<1536, 256>>>(2, SBS, 0, 0, 95, 2, DM, c3b, 3, SBS, DM, 0, 96, 40, 1);
    convgemm<<<dim3(1536, 3), 256>>>(3, SBS, 2, 0, 95, 3, G3, gbi, 8, GBS, G3, 0, 96, 8, 0);

    // left-boundary cascades for all 48 windows
    lbgemm<0><<<1536, 256>>>(c1b);
    lbgemm<1><<<3072, 256>>>(c2b);
    lbgemm<2><<<4608, 256>>>(c3b);
    lbgemm<3><<<dim3(4608, 3), 256>>>(gbi);

    // all 48 autoregressive steps in one persistent kernel
    loop_kernel<<<BB / 4, 384>>>(gWh, gbh, fcw, fcb, b_val, c1b, c2b, c3b, gbi, out);
}

// round 13
// speedup vs baseline: 1.0418x; 1.0418x over previous
#include <cuda_runtime.h>

#define BB    512
#define SEQL  96
#define PREDL 48
#define TOTL  144
#define CIN   7
#define DM    128
#define G3    384
#define KSZ   5
#define PADL  2
#define NWIN  48
#define WCONV (KSZ*DM*DM)   // 81920

// ---------------- device scratch ----------------
__device__ float g_temb[BB * TOTL * DM];
__device__ float g_xcat[BB * TOTL * CIN];
__device__ float g_emb [BB * TOTL * DM];
__device__ float g_c1  [BB * TOTL * DM];
__device__ float g_c2  [BB * TOTL * DM];
__device__ float g_c3  [BB * TOTL * DM];
__device__ float g_gx  [BB * TOTL * G3];
__device__ float g_lbgx[(size_t)PREDL * BB * 6 * G3];
__device__ float g_lb1 [BB * NWIN * 2 * DM];
__device__ float g_lb2 [BB * NWIN * 4 * DM];
__device__ float g_lb3 [BB * NWIN * 6 * DM];
__device__ float g_wc  [3 * WCONV];          // [sel][tap*128+ic][o]
__device__ float g_wvt [CIN * DM];
__device__ float g_wit [DM * G3];            // Wi^T [d][g]

__device__ __forceinline__ float* sel_buf(int s) {
    switch (s) {
        case 0: return g_emb; case 1: return g_c1; case 2: return g_c2;
        case 3: return g_c3;  default: return g_gx;
    }
}
__device__ __forceinline__ const float* sel_w(int s) {
    return (s < 3) ? (g_wc + s * WCONV) : g_wit;
}

__device__ __forceinline__ void ffma2(unsigned long long& acc,
                                      unsigned long long a, unsigned long long w) {
    asm("fma.rn.f32x2 %0, %1, %2, %0;" : "+l"(acc) : "l"(a), "l"(w));
}
__device__ __forceinline__ float sum2(unsigned long long v) {
    float2 f = *reinterpret_cast<float2*>(&v);
    return f.x + f.y;
}

// ---------------- prep ----------------
__global__ void pack_kernel(const float* __restrict__ w1, const float* __restrict__ w2,
                            const float* __restrict__ w3, const float* __restrict__ wval,
                            const float* __restrict__ wi) {
    int idx = blockIdx.x * 256 + threadIdx.x;
    if (idx < WCONV) {
        int r = idx / DM, o = idx - r * DM;
        int k = r / DM,  i = r - k * DM;
        int s = (o * DM + i) * KSZ + k;
        g_wc[idx]             = w1[s];
        g_wc[WCONV + idx]     = w2[s];
        g_wc[2 * WCONV + idx] = w3[s];
    }
    if (idx < DM * G3) {
        int d = idx / G3, g = idx - d * G3;
        g_wit[idx] = wi[g * DM + d];
    }
    if (idx < CIN * DM) {
        int c = idx / DM, d = idx - c * DM;
        g_wvt[idx] = wval[d * CIN + c];
    }
}

__global__ void temb_kernel(const int* __restrict__ ymark,
                            const float* __restrict__ hour, const float* __restrict__ wk,
                            const float* __restrict__ day,  const float* __restrict__ mon) {
    int bl = blockIdx.x, d = threadIdx.x;
    const int* y = ymark + bl * 4;
    g_temb[bl * DM + d] = hour[y[0] * DM + d] + wk[y[1] * DM + d]
                        + day [y[2] * DM + d] + mon[y[3] * DM + d];
}

__global__ void initx_kernel(const float* __restrict__ xenc) {
    int idx = blockIdx.x * 256 + threadIdx.x;
    if (idx >= BB * TOTL * CIN) return;
    int c = idx % CIN;
    int t = (idx / CIN) % TOTL;
    int b = idx / (CIN * TOTL);
    g_xcat[idx] = (t < SEQL) ? xenc[(b * SEQL + t) * CIN + c] : 0.f;
}

__global__ void embed_kernel(const float* __restrict__ bval) {
    int bl = blockIdx.x;                       // b*SEQL + p
    int b = bl / SEQL, p = bl - b * SEQL;
    int d = threadIdx.x;
    __shared__ float xs[CIN];
    if (d < CIN) xs[d] = g_xcat[(b * TOTL + p) * CIN + d];
    __syncthreads();
    float acc = bval[d] + g_temb[(b * TOTL + p) * DM + d];
#pragma unroll
    for (int c = 0; c < CIN; c++) acc = fmaf(xs[c], g_wvt[c * DM + d], acc);
    g_emb[(b * TOTL + p) * DM + d] = acc;
}

// ---------------- tiled GEMM for the initial full pass ----------------
__global__ __launch_bounds__(256) void convgemm(
    int ssel, int srcBS, int pbase, int qlo, int qhi,
    int wsel, int Nw, const float* __restrict__ bias,
    int dsel, int dstBS, int dstPS, int dstPB,
    int npos, int KC, int relu)
{
    const float* __restrict__ src = sel_buf(ssel);
    const float* __restrict__ w   = sel_w(wsel);
    float*       __restrict__ dst = sel_buf(dsel);

    __shared__ float As[16][33];
    __shared__ float Bs[16][DM];

    int tid = threadIdx.x;
    int tx = tid & 15, ty = tid >> 4;
    int ncol0 = blockIdx.y * DM;

    int R0 = blockIdx.x * 32 + ty;
    int R1 = R0 + 16;
    int b0 = R0 / npos, p0 = R0 - b0 * npos;
    int b1 = R1 / npos, p1 = R1 - b1 * npos;
    const float* s0 = src + (size_t)b0 * srcBS;
    const float* s1 = src + (size_t)b1 * srcBS;
    int pr0 = pbase + p0 - PADL;
    int pr1 = pbase + p1 - PADL;

    float acc[2][8];
#pragma unroll
    for (int m = 0; m < 2; m++)
#pragma unroll
        for (int n = 0; n < 8; n++) acc[m][n] = 0.f;

    for (int kc = 0; kc < KC; kc++) {
        int tap = kc >> 3;
        int icb = (kc & 7) << 4;
        int q0 = pr0 + tap, q1 = pr1 + tap;
        float v0 = (q0 >= qlo && q0 <= qhi) ? s0[(size_t)q0 * DM + icb + tx] : 0.f;
        float v1 = (q1 >= qlo && q1 <= qhi) ? s1[(size_t)q1 * DM + icb + tx] : 0.f;
        As[tx][ty]      = v0;
        As[tx][ty + 16] = v1;
#pragma unroll
        for (int qq = 0; qq < 8; qq++) {
            int e = tid + 256 * qq;
            int kk = e >> 7, o = e & 127;
            Bs[kk][o] = w[(size_t)(kc * 16 + kk) * Nw + ncol0 + o];
        }
        __syncthreads();
#pragma unroll
        for (int rr = 0; rr < 16; rr++) {
            float a0 = As[rr][ty], a1 = As[rr][ty + 16];
            float bv[8];
#pragma unroll
            for (int n = 0; n < 8; n++) bv[n] = Bs[rr][tx + 16 * n];
#pragma unroll
            for (int n = 0; n < 8; n++) {
                acc[0][n] = fmaf(a0, bv[n], acc[0][n]);
                acc[1][n] = fmaf(a1, bv[n], acc[1][n]);
            }
        }
        __syncthreads();
    }
#pragma unroll
    for (int m = 0; m < 2; m++) {
        int b = m ? b1 : b0;
        int pi = m ? p1 : p0;
        float* dp = dst + (size_t)b * dstBS + (size_t)(dstPB + pi) * dstPS + ncol0;
#pragma unroll
        for (int n = 0; n < 8; n++) {
            int o = tx + 16 * n;
            float v = acc[m][n] + bias[ncol0 + o];
            dp[o] = relu ? fmaxf(v, 0.f) : v;
        }
    }
}

// ---------------- left-boundary cascades as 4 chip-wide GEMMs ----------------
template<int ST>
__device__ __forceinline__ float lb_fetch(int b, int win, int a, int ic) {
    if (ST == 0) return (a >= 0) ? g_emb[((size_t)b * TOTL + win + a) * DM + ic] : 0.f;
    if (ST == 1) {
        if (a < 0) return 0.f;
        return (a < 2) ? g_lb1[(((size_t)b * NWIN + win) * 2 + a) * DM + ic]
                       : g_c1[((size_t)b * TOTL + win + a) * DM + ic];
    }
    if (a < 0) return 0.f;
    return (a < 4) ? g_lb2[(((size_t)b * NWIN + win) * 4 + a) * DM + ic]
                   : g_c2[((size_t)b * TOTL + win + a) * DM + ic];
}

template<int ST>
__global__ __launch_bounds__(256) void lbgemm(const float* __restrict__ bias) {
    constexpr int NPOS = (ST == 0) ? 2 : (ST == 1) ? 4 : 6;
    constexpr int KC   = (ST == 3) ? 8 : 40;
    constexpr int NW   = (ST == 3) ? G3 : DM;

    __shared__ float As[16][33];
    __shared__ float Bs[16][DM];

    int tid = threadIdx.x;
    int tx = tid & 15, ty = tid >> 4;
    int ncol0 = blockIdx.y * DM;
    const float* __restrict__ w = (ST == 3) ? g_wit : (g_wc + ST * WCONV);

    int R0 = blockIdx.x * 32 + ty, R1 = R0 + 16;
    int p0 = R0 % NPOS, wb0 = R0 / NPOS, win0 = wb0 % NWIN, b0 = wb0 / NWIN;
    int p1 = R1 % NPOS, wb1 = R1 / NPOS, win1 = wb1 % NWIN, b1 = wb1 / NWIN;

    float acc[2][8];
#pragma unroll
    for (int m = 0; m < 2; m++)
#pragma unroll
        for (int n = 0; n < 8; n++) acc[m][n] = 0.f;

    for (int kc = 0; kc < KC; kc++) {
        int tap = kc >> 3;
        int ic  = ((kc & 7) << 4) + tx;
        float v0, v1;
        if (ST == 3) {
            v0 = g_lb3[(((size_t)b0 * NWIN + win0) * 6 + p0) * DM + ic];
            v1 = g_lb3[(((size_t)b1 * NWIN + win1) * 6 + p1) * DM + ic];
        } else {
            v0 = lb_fetch<ST>(b0, win0, p0 + tap - PADL, ic);
            v1 = lb_fetch<ST>(b1, win1, p1 + tap - PADL, ic);
        }
        As[tx][ty]      = v0;
        As[tx][ty + 16] = v1;
#pragma unroll
        for (int qq = 0; qq < 8; qq++) {
            int e = tid + 256 * qq;
            int kk = e >> 7, o = e & 127;
            Bs[kk][o] = w[(size_t)(kc * 16 + kk) * NW + ncol0 + o];
        }
        __syncthreads();
#pragma unroll
        for (int rr = 0; rr < 16; rr++) {
            float a0 = As[rr][ty], a1 = As[rr][ty + 16];
            float bv[8];
#pragma unroll
            for (int n = 0; n < 8; n++) bv[n] = Bs[rr][tx + 16 * n];
#pragma unroll
            for (int n = 0; n < 8; n++) {
                acc[0][n] = fmaf(a0, bv[n], acc[0][n]);
                acc[1][n] = fmaf(a1, bv[n], acc[1][n]);
            }
        }
        __syncthreads();
    }
#pragma unroll
    for (int m = 0; m < 2; m++) {
        int b = m ? b1 : b0, win = m ? win1 : win0, p = m ? p1 : p0;
#pragma unroll
        for (int n = 0; n < 8; n++) {
            int o = tx + 16 * n;
            float v = acc[m][n] + bias[ncol0 + o];
            if (ST == 0) g_lb1[(((size_t)b * NWIN + win) * 2 + p) * DM + o] = fmaxf(v, 0.f);
            if (ST == 1) g_lb2[(((size_t)b * NWIN + win) * 4 + p) * DM + o] = fmaxf(v, 0.f);
            if (ST == 2) g_lb3[(((size_t)b * NWIN + win) * 6 + p) * DM + o] = fmaxf(v, 0.f);
            if (ST == 3) g_lbgx[(((size_t)win * BB + b) * 6 + p) * G3 + ncol0 + o] = v;
        }
    }
}

// ---------------- prologue conv stage (384 threads, 3-way ic split; R6/R10-proven) ----------------
template<int NPOS>
__device__ __forceinline__ void prolog_stage(int b0, int F,
        const float* __restrict__ src, const float* __restrict__ wp,
        const float* __restrict__ bias, float* __restrict__ dst,
        float* sA4, float* sRedA, float* sRedB,
        int tid, int o, int g, int ic0, int ic1) {
    constexpr int NR = NPOS + 2;
    for (int e = tid; e < 4 * NR * DM; e += 384) {
        int ic = e & 127, ra = e >> 7;
        int r = ra / NR, a = ra - r * NR;
        sA4[e] = src[((size_t)(b0 + r) * TOTL + F - (NR - 1) + a) * DM + ic];
    }
    __syncthreads();
    float acc[NPOS][4];
#pragma unroll
    for (int p = 0; p < NPOS; p++)
#pragma unroll
        for (int r = 0; r < 4; r++) acc[p][r] = 0.f;
    for (int ic = ic0; ic < ic1; ic++) {
        float xv[4][NR];
#pragma unroll
        for (int r = 0; r < 4; r++)
#pragma unroll
            for (int a = 0; a < NR; a++) xv[r][a] = sA4[(r * NR + a) * DM + ic];
#pragma unroll
        for (int tap = 0; tap < 5; tap++) {
            float w = wp[(size_t)(tap * DM + ic) * DM + o];
#pragma unroll
            for (int p = 0; p < NPOS; p++) {
                const int a = p + tap;
                if (a <= NPOS + 1) {
#pragma unroll
                    for (int r = 0; r < 4; r++)
                        acc[p][r] = fmaf(w, xv[r][a], acc[p][r]);
                }
            }
        }
    }
    for (int r = 0; r < 4; r++) {
        if (g == 1) {
#pragma unroll
            for (int p = 0; p < NPOS; p++) sRedA[p * DM + o] = acc[p][r];
        } else if (g == 2) {
#pragma unroll
            for (int p = 0; p < NPOS; p++) sRedB[p * DM + o] = acc[p][r];
        }
        __syncthreads();
        if (g == 0) {
#pragma unroll
            for (int p = 0; p < NPOS; p++) {
                float v = acc[p][r] + sRedA[p * DM + o] + sRedB[p * DM + o] + bias[o];
                dst[((size_t)(b0 + r) * TOTL + F - (NPOS - 1) + p) * DM + o] = fmaxf(v, 0.f);
            }
        }
        __syncthreads();
    }
}

// ---------------- persistent loop: 48 steps, uniform 384 threads ----------------
__global__ __launch_bounds__(384, 1) void loop_kernel(
        const float* __restrict__ Wh,  const float* __restrict__ bh,
        const float* __restrict__ fcw, const float* __restrict__ fcb,
        const float* __restrict__ bval,
        const float* __restrict__ c1b, const float* __restrict__ c2b,
        const float* __restrict__ c3b, const float* __restrict__ gbi,
        float* __restrict__ dout) {
    int tid = threadIdx.x;
    int b0  = blockIdx.x * 4;

    __shared__ __align__(16) float h_s[4][DM];
    __shared__ float S1[4][G3];
    __shared__ float S2[4][DM];
    __shared__ float sPred[4][CIN];
    __shared__ __align__(16) float sA4[4 * 9 * DM];
    __shared__ float sRedA[7 * DM];
    __shared__ float sRedB[7 * DM];

    for (int i = 0; i < PREDL; i++) {
        if (i > 0) {
            __syncthreads();   // sPred(i-1) visible, h_s/S1 free for reuse
            const int F  = SEQL - 1 + i;
            const int o  = tid & 127;
            const int g  = tid >> 7;
            const int ic0 = (g == 0) ? 0 : (g == 1) ? 43 : 86;
            const int ic1 = (g == 0) ? 43 : (g == 1) ? 86 : 128;

            // embedding at frontier F from sPred
            for (int e = tid; e < 4 * DM; e += 384) {
                int r = e >> 7, d = e & 127;
                int b = b0 + r;
                float a = bval[d] + g_temb[((size_t)b * TOTL + F) * DM + d];
#pragma unroll
                for (int c = 0; c < CIN; c++) a = fmaf(sPred[r][c], g_wvt[c * DM + d], a);
                g_emb[((size_t)b * TOTL + F) * DM + d] = a;
            }
            __syncthreads();

            prolog_stage<3>(b0, F, g_emb, g_wc,             c1b, g_c1, sA4, sRedA, sRedB, tid, o, g, ic0, ic1);
            prolog_stage<5>(b0, F, g_c1,  g_wc + WCONV,     c2b, g_c2, sA4, sRedA, sRedB, tid, o, g, ic0, ic1);
            prolog_stage<7>(b0, F, g_c2,  g_wc + 2 * WCONV, c3b, g_c3, sA4, sRedA, sRedB, tid, o, g, ic0, ic1);

            // gx at F-6..F: rows split 4-way, cols in float4 quads
            for (int e = tid; e < 4 * 7 * DM; e += 384) {
                int ic = e & 127, rp = e >> 7;
                int r = rp / 7, p = rp - r * 7;
                sA4[e] = g_c3[((size_t)(b0 + r) * TOTL + F - 6 + p) * DM + ic];
            }
            __syncthreads();
            {
                int rq = tid / 96, cq = tid - rq * 96;
                float acc[7][4];
#pragma unroll
                for (int p = 0; p < 7; p++)
#pragma unroll
                    for (int c = 0; c < 4; c++) acc[p][c] = 0.f;
                const float4* wv = reinterpret_cast<const float4*>(g_wit) + cq;
                const float* xb = sA4 + rq * 7 * DM;
                for (int k = 0; k < DM; k++) {
                    float4 w = wv[(size_t)k * 96];
                    float x[7];
#pragma unroll
                    for (int p = 0; p < 7; p++) x[p] = xb[p * DM + k];
#pragma unroll
                    for (int p = 0; p < 7; p++) {
                        acc[p][0] = fmaf(w.x, x[p], acc[p][0]);
                        acc[p][1] = fmaf(w.y, x[p], acc[p][1]);
                        acc[p][2] = fmaf(w.z, x[p], acc[p][2]);
                        acc[p][3] = fmaf(w.w, x[p], acc[p][3]);
                    }
                }
                float4 bo = reinterpret_cast<const float4*>(gbi)[cq];
#pragma unroll
                for (int p = 0; p < 7; p++) {
                    float4 v;
                    v.x = acc[p][0] + bo.x; v.y = acc[p][1] + bo.y;
                    v.z = acc[p][2] + bo.z; v.w = acc[p][3] + bo.w;
                    *reinterpret_cast<float4*>(
                        g_gx + ((size_t)(b0 + rq) * TOTL + F - 6 + p) * G3 + cq * 4) = v;
                }
            }
            __syncthreads();
        }

        // ---- GRU t-loop ----
        int j = tid;
        ulonglong2 wr[32];
        {
            const ulonglong2* p = reinterpret_cast<const ulonglong2*>(Wh + (size_t)j * DM);
#pragma unroll
            for (int q = 0; q < 32; q++) wr[q] = p[q];
        }
        float bhj = bh[j];

        for (int e = j; e < 4 * DM; e += 384) (&h_s[0][0])[e] = 0.f;
        __syncthreads();

        // preload gx for t = 0
        float gxv[4];
#pragma unroll
        for (int r = 0; r < 4; r++)
            gxv[r] = g_lbgx[(((size_t)i * BB + b0 + r) * 6 + 0) * G3 + j];

        for (int t = 0; t < SEQL; t++) {
            // prefetch next-t gx early; load latency covered by the FFMA2 chain below
            float gxn[4] = {0.f, 0.f, 0.f, 0.f};
            if (t + 1 < SEQL) {
#pragma unroll
                for (int r = 0; r < 4; r++) {
                    int b = b0 + r;
                    gxn[r] = (t + 1 < 6)
                        ? g_lbgx[(((size_t)i * BB + b) * 6 + (t + 1)) * G3 + j]
                        : g_gx[((size_t)b * TOTL + i + t + 1) * G3 + j];
                }
            }
            unsigned long long c0 = 0, c1 = 0, c2 = 0, c3 = 0;
            const ulonglong2* h0 = reinterpret_cast<const ulonglong2*>(h_s[0]);
            const ulonglong2* h1 = reinterpret_cast<const ulonglong2*>(h_s[1]);
            const ulonglong2* h2 = reinterpret_cast<const ulonglong2*>(h_s[2]);
            const ulonglong2* h3 = reinterpret_cast<const ulonglong2*>(h_s[3]);
#pragma unroll
            for (int q = 0; q < 32; q++) {
                ulonglong2 w  = wr[q];
                ulonglong2 x0 = h0[q], x1 = h1[q], x2 = h2[q], x3 = h3[q];
                ffma2(c0, x0.x, w.x); ffma2(c0, x0.y, w.y);
                ffma2(c1, x1.x, w.x); ffma2(c1, x1.y, w.y);
                ffma2(c2, x2.x, w.x); ffma2(c2, x2.y, w.y);
                ffma2(c3, x3.x, w.x); ffma2(c3, x3.y, w.y);
            }
            float accs[4] = {sum2(c0), sum2(c1), sum2(c2), sum2(c3)};
#pragma unroll
            for (int r = 0; r < 4; r++) {
                float gh = accs[r] + bhj;
                if (j < 2 * DM) S1[r][j] = gxv[r] + gh;
                else            { S1[r][j] = gh; S2[r][j - 2 * DM] = gxv[r]; }
            }
            __syncthreads();
            for (int e = j; e < 4 * DM; e += 384) {
                int r = e >> 7, d = e & 127;
                float rg = __fdividef(1.f, 1.f + __expf(-S1[r][d]));
                float zg = __fdividef(1.f, 1.f + __expf(-S1[r][DM + d]));
                float na = S2[r][d] + rg * S1[r][2 * DM + d];
                float ng = 1.f - __fdividef(2.f, __expf(2.f * na) + 1.f);
                h_s[r][d] = (1.f - zg) * ng + zg * h_s[r][d];
            }
            __syncthreads();
#pragma unroll
            for (int r = 0; r < 4; r++) gxv[r] = gxn[r];
        }

        if (j < 4 * CIN) {
            int r = j / CIN, c = j - r * CIN;
            float acc = fcb[c];
            for (int d = 0; d < DM; d++) acc = fmaf(h_s[r][d], fcw[c * DM + d], acc);
            sPred[r][c] = acc;
            dout[((size_t)(b0 + r) * PREDL + i) * CIN + c] = acc;
        }
    }
}

// ---------------- launcher ----------------
extern "C" void kernel_launch(void* const* d_in, const int* in_sizes, int n_in,
                              void* d_out, int out_size) {
    (void)in_sizes; (void)n_in; (void)out_size;
    const float* x_enc  = (const float*)d_in[0];
    const int*   y_mark = (const int*)  d_in[2];
    const float* hour_e = (const float*)d_in[3];
    const float* wk_e   = (const float*)d_in[4];
    const float* day_e  = (const float*)d_in[5];
    const float* mon_e  = (const float*)d_in[6];
    const float* W_val  = (const float*)d_in[7];
    const float* b_val  = (const float*)d_in[8];
    const float* c1w    = (const float*)d_in[9];
    const float* c1b    = (const float*)d_in[10];
    const float* c2w    = (const float*)d_in[11];
    const float* c2b    = (const float*)d_in[12];
    const float* c3w    = (const float*)d_in[13];
    const float* c3b    = (const float*)d_in[14];
    const float* gWi    = (const float*)d_in[15];
    const float* gWh    = (const float*)d_in[16];
    const float* gbi    = (const float*)d_in[17];
    const float* gbh    = (const float*)d_in[18];
    const float* fcw    = (const float*)d_in[19];
    const float* fcb    = (const float*)d_in[20];
    float* out = (float*)d_out;

    const int SBS = TOTL * DM;
    const int GBS = TOTL * G3;

    pack_kernel<<<(WCONV + 255) / 256, 256>>>(c1w, c2w, c3w, W_val, gWi);
    temb_kernel<<<BB * TOTL, DM>>>(y_mark, hour_e, wk_e, day_e, mon_e);
    initx_kernel<<<(BB * TOTL * CIN + 255) / 256, 256>>>(x_enc);
    embed_kernel<<<BB * SEQL, DM>>>(b_val);

    // initial full pass over positions [0,95]
    convgemm<<<1536, 256>>>(0, SBS, 0, 0, 95, 0, DM, c1b, 1, SBS, DM, 0, 96, 40, 1);
    convgemm<<<1536, 256>>>(1, SBS, 0, 0, 95, 1, DM, c2b, 2, SBS, DM, 0, 96, 40, 1);
    convgemm<<<1536, 256>>>(2, SBS, 0, 0, 95, 2, DM, c3b, 3, SBS, DM, 0, 96, 40, 1);
    convgemm<<<dim3(1536, 3), 256>>>(3, SBS, 2, 0, 95, 3, G3, gbi, 8, GBS, G3, 0, 96, 8, 0);

    // left-boundary cascades for all 48 windows
    lbgemm<0><<<1536, 256>>>(c1b);
    lbgemm<1><<<3072, 256>>>(c2b);
    lbgemm<2><<<4608, 256>>>(c3b);
    lbgemm<3><<<dim3(4608, 3), 256>>>(gbi);

    // all 48 autoregressive steps in one persistent kernel (no inter-block sync)
    loop_kernel<<<BB / 4, 384>>>(gWh, gbh, fcw, fcb, b_val, c1b, c2b, c3b, gbi, out);
}

// round 16
// speedup vs baseline: 1.1427x; 1.0969x over previous
#include <cuda_runtime.h>

#define BB    512
#define SEQL  96
#define PREDL 48
#define TOTL  144
#define CIN   7
#define DM    128
#define G3    384
#define KSZ   5
#define PADL  2
#define NWIN  48
#define WCONV (KSZ*DM*DM)   // 81920
#define MAINB 1536          // blocks covering 512*96 main rows / 32

// ---------------- device scratch ----------------
__device__ float g_temb[BB * TOTL * DM];
__device__ float g_xcat[BB * TOTL * CIN];
__device__ float g_emb [BB * TOTL * DM];
__device__ float g_c1  [BB * TOTL * DM];
__device__ float g_c2  [BB * TOTL * DM];
__device__ float g_c3  [BB * TOTL * DM];
__device__ float g_gx  [BB * TOTL * G3];
__device__ float g_lbgx[(size_t)PREDL * BB * 6 * G3];
__device__ float g_lb1 [BB * NWIN * 2 * DM];
__device__ float g_lb2 [BB * NWIN * 4 * DM];
__device__ float g_lb3 [BB * NWIN * 6 * DM];
__device__ float g_wc  [3 * WCONV];          // [sel][tap*128+ic][o]
__device__ float g_wvt [CIN * DM];
__device__ float g_wit [DM * G3];            // Wi^T [d][g]

__device__ __forceinline__ void ffma2(unsigned long long& acc,
                                      unsigned long long a, unsigned long long w) {
    asm("fma.rn.f32x2 %0, %1, %2, %0;" : "+l"(acc) : "l"(a), "l"(w));
}
__device__ __forceinline__ float sum2(unsigned long long v) {
    float2 f = *reinterpret_cast<float2*>(&v);
    return f.x + f.y;
}

// ---------------- prep (merged) ----------------
// P1: pack weights + init xcat, one launch (independent outputs)
__global__ void prep1_kernel(const float* __restrict__ w1, const float* __restrict__ w2,
                             const float* __restrict__ w3, const float* __restrict__ wval,
                             const float* __restrict__ wi, const float* __restrict__ xenc) {
    int idx = blockIdx.x * 256 + threadIdx.x;
    if (idx < WCONV) {
        int r = idx / DM, o = idx - r * DM;
        int k = r / DM,  i = r - k * DM;
        int s = (o * DM + i) * KSZ + k;
        g_wc[idx]             = w1[s];
        g_wc[WCONV + idx]     = w2[s];
        g_wc[2 * WCONV + idx] = w3[s];
    }
    if (idx < DM * G3) {
        int d = idx / G3, g = idx - d * G3;
        g_wit[idx] = wi[g * DM + d];
    }
    if (idx < CIN * DM) {
        int c = idx / DM, d = idx - c * DM;
        g_wvt[idx] = wval[d * CIN + c];
    }
    if (idx < BB * TOTL * CIN) {
        int c = idx % CIN;
        int t = (idx / CIN) % TOTL;
        int b = idx / (CIN * TOTL);
        g_xcat[idx] = (t < SEQL) ? xenc[(b * SEQL + t) * CIN + c] : 0.f;
    }
}

// P2: temporal embedding (all TOTL positions) + value embedding (first SEQL)
__global__ void prep2_kernel(const int* __restrict__ ymark,
                             const float* __restrict__ hour, const float* __restrict__ wk,
                             const float* __restrict__ day,  const float* __restrict__ mon,
                             const float* __restrict__ bval) {
    int bl = blockIdx.x;                  // b*TOTL + l
    int b = bl / TOTL, l = bl - b * TOTL;
    int d = threadIdx.x;
    __shared__ float xs[CIN];
    if (d < CIN && l < SEQL) xs[d] = g_xcat[bl * CIN + d];
    const int* y = ymark + bl * 4;
    float te = hour[y[0] * DM + d] + wk[y[1] * DM + d]
             + day [y[2] * DM + d] + mon[y[3] * DM + d];
    g_temb[bl * DM + d] = te;
    __syncthreads();
    if (l < SEQL) {
        float acc = bval[d] + te;
#pragma unroll
        for (int c = 0; c < CIN; c++) acc = fmaf(xs[c], g_wvt[c * DM + d], acc);
        g_emb[bl * DM + d] = acc;
    }
}

// ---------------- fused stage GEMMs: main conv rows + paired lb rows ----------------
template<int ST>
__device__ __forceinline__ float lb_fetch(int b, int win, int a, int ic) {
    if (ST == 0) return (a >= 0) ? g_emb[((size_t)b * TOTL + win + a) * DM + ic] : 0.f;
    if (ST == 1) {
        if (a < 0) return 0.f;
        return (a < 2) ? g_lb1[(((size_t)b * NWIN + win) * 2 + a) * DM + ic]
                       : g_c1[((size_t)b * TOTL + win + a) * DM + ic];
    }
    if (a < 0) return 0.f;
    return (a < 4) ? g_lb2[(((size_t)b * NWIN + win) * 4 + a) * DM + ic]
                   : g_c2[((size_t)b * TOTL + win + a) * DM + ic];
}

// ST 0/1/2: conv stage ST main (96 pos/batch) + lbgemm<ST> rows; N=128, KC=40, relu.
// ST 3:     gx main (pointwise, N=384, KC=8) + lbgemm<3> rows; no relu.
template<int ST>
__global__ __launch_bounds__(256) void stage_kernel(const float* __restrict__ bias) {
    constexpr bool GX  = (ST == 3);
    constexpr int KC   = GX ? 8 : 40;
    constexpr int NW   = GX ? G3 : DM;
    constexpr int NPOS = (ST == 0) ? 2 : (ST == 1) ? 4 : 6;  // lb rows per window

    __shared__ float As[16][33];
    __shared__ float Bs[16][DM];

    int tid = threadIdx.x;
    int tx = tid & 15, ty = tid >> 4;
    int ncol0 = blockIdx.y * DM;
    const float* __restrict__ w = GX ? g_wit : (g_wc + ST * WCONV);
    const float* __restrict__ src =
        (ST == 0) ? g_emb : (ST == 1) ? g_c1 : (ST == 2) ? g_c2 : g_c3;

    const bool isMain = blockIdx.x < MAINB;
    int bx = isMain ? blockIdx.x : blockIdx.x - MAINB;

    // row decode for the two 16-row halves
    int b[2], p[2], win[2];
#pragma unroll
    for (int m = 0; m < 2; m++) {
        int R = bx * 32 + ty + m * 16;
        if (isMain) { b[m] = R / SEQL; p[m] = R - b[m] * SEQL; win[m] = 0; }
        else {
            p[m] = R % NPOS;
            int wb = R / NPOS;
            win[m] = wb % NWIN;
            b[m] = wb / NWIN;
        }
    }

    float acc[2][8];
#pragma unroll
    for (int m = 0; m < 2; m++)
#pragma unroll
        for (int n = 0; n < 8; n++) acc[m][n] = 0.f;

    for (int kc = 0; kc < KC; kc++) {
        int tap = kc >> 3;
        int ic  = ((kc & 7) << 4) + tx;
        float v[2];
#pragma unroll
        for (int m = 0; m < 2; m++) {
            if (GX) {
                v[m] = isMain
                    ? g_c3[((size_t)b[m] * TOTL + p[m]) * DM + ic]
                    : g_lb3[(((size_t)b[m] * NWIN + win[m]) * 6 + p[m]) * DM + ic];
            } else if (isMain) {
                int q = p[m] - PADL + tap;
                v[m] = (q >= 0 && q <= SEQL - 1)
                    ? src[((size_t)b[m] * TOTL + q) * DM + ic] : 0.f;
            } else {
                v[m] = lb_fetch<ST == 3 ? 2 : ST>(b[m], win[m], p[m] + tap - PADL, ic);
            }
        }
        As[tx][ty]      = v[0];
        As[tx][ty + 16] = v[1];
#pragma unroll
        for (int qq = 0; qq < 8; qq++) {
            int e = tid + 256 * qq;
            int kk = e >> 7, o = e & 127;
            Bs[kk][o] = w[(size_t)(kc * 16 + kk) * NW + ncol0 + o];
        }
        __syncthreads();
#pragma unroll
        for (int rr = 0; rr < 16; rr++) {
            float a0 = As[rr][ty], a1 = As[rr][ty + 16];
            float bv[8];
#pragma unroll
            for (int n = 0; n < 8; n++) bv[n] = Bs[rr][tx + 16 * n];
#pragma unroll
            for (int n = 0; n < 8; n++) {
                acc[0][n] = fmaf(a0, bv[n], acc[0][n]);
                acc[1][n] = fmaf(a1, bv[n], acc[1][n]);
            }
        }
        __syncthreads();
    }
#pragma unroll
    for (int m = 0; m < 2; m++) {
#pragma unroll
        for (int n = 0; n < 8; n++) {
            int o = tx + 16 * n;
            float v = acc[m][n] + bias[ncol0 + o];
            if (GX) {
                if (isMain)
                    g_gx[((size_t)b[m] * TOTL + p[m]) * G3 + ncol0 + o] = v;
                else
                    g_lbgx[(((size_t)win[m] * BB + b[m]) * 6 + p[m]) * G3 + ncol0 + o] = v;
            } else {
                v = fmaxf(v, 0.f);
                if (isMain) {
                    float* dst = (ST == 0) ? g_c1 : (ST == 1) ? g_c2 : g_c3;
                    dst[((size_t)b[m] * TOTL + p[m]) * DM + o] = v;
                } else {
                    if (ST == 0) g_lb1[(((size_t)b[m] * NWIN + win[m]) * 2 + p[m]) * DM + o] = v;
                    if (ST == 1) g_lb2[(((size_t)b[m] * NWIN + win[m]) * 4 + p[m]) * DM + o] = v;
                    if (ST == 2) g_lb3[(((size_t)b[m] * NWIN + win[m]) * 6 + p[m]) * DM + o] = v;
                }
            }
        }
    }
}

// ---------------- prologue conv stage (R10-verbatim) ----------------
template<int NPOS>
__device__ __forceinline__ void prolog_stage(int b0, int F,
        const float* __restrict__ src, const float* __restrict__ wp,
        const float* __restrict__ bias, float* __restrict__ dst,
        float* sA4, float* sRedA, float* sRedB,
        int tid, int o, int g, int ic0, int ic1) {
    constexpr int NR = NPOS + 2;
    for (int e = tid; e < 4 * NR * DM; e += 384) {
        int ic = e & 127, ra = e >> 7;
        int r = ra / NR, a = ra - r * NR;
        sA4[e] = src[((size_t)(b0 + r) * TOTL + F - (NR - 1) + a) * DM + ic];
    }
    __syncthreads();
    float acc[NPOS][4];
#pragma unroll
    for (int p = 0; p < NPOS; p++)
#pragma unroll
        for (int r = 0; r < 4; r++) acc[p][r] = 0.f;
    for (int ic = ic0; ic < ic1; ic++) {
        float xv[4][NR];
#pragma unroll
        for (int r = 0; r < 4; r++)
#pragma unroll
            for (int a = 0; a < NR; a++) xv[r][a] = sA4[(r * NR + a) * DM + ic];
#pragma unroll
        for (int tap = 0; tap < 5; tap++) {
            float w = wp[(size_t)(tap * DM + ic) * DM + o];
#pragma unroll
            for (int p = 0; p < NPOS; p++) {
                const int a = p + tap;
                if (a <= NPOS + 1) {
#pragma unroll
                    for (int r = 0; r < 4; r++)
                        acc[p][r] = fmaf(w, xv[r][a], acc[p][r]);
                }
            }
        }
    }
    for (int r = 0; r < 4; r++) {
        if (g == 1) {
#pragma unroll
            for (int p = 0; p < NPOS; p++) sRedA[p * DM + o] = acc[p][r];
        } else if (g == 2) {
#pragma unroll
            for (int p = 0; p < NPOS; p++) sRedB[p * DM + o] = acc[p][r];
        }
        __syncthreads();
        if (g == 0) {
#pragma unroll
            for (int p = 0; p < NPOS; p++) {
                float v = acc[p][r] + sRedA[p * DM + o] + sRedB[p * DM + o] + bias[o];
                dst[((size_t)(b0 + r) * TOTL + F - (NPOS - 1) + p) * DM + o] = fmaxf(v, 0.f);
            }
        }
        __syncthreads();
    }
}

// ---------------- persistent loop: 48 steps (R10-verbatim) ----------------
__global__ __launch_bounds__(384, 1) void loop_kernel(
        const float* __restrict__ Wh,  const float* __restrict__ bh,
        const float* __restrict__ fcw, const float* __restrict__ fcb,
        const float* __restrict__ bval,
        const float* __restrict__ c1b, const float* __restrict__ c2b,
        const float* __restrict__ c3b, const float* __restrict__ gbi,
        float* __restrict__ dout) {
    int tid = threadIdx.x;
    int b0  = blockIdx.x * 4;

    __shared__ __align__(16) float h_s[4][DM];
    __shared__ float S1[4][G3];
    __shared__ float S2[4][DM];
    __shared__ float sPred[4][CIN];
    __shared__ __align__(16) float sA4[4 * 9 * DM];
    __shared__ float sRedA[7 * DM];
    __shared__ float sRedB[7 * DM];

    for (int i = 0; i < PREDL; i++) {
        if (i > 0) {
            __syncthreads();
            const int F  = SEQL - 1 + i;
            const int o  = tid & 127;
            const int g  = tid >> 7;
            const int ic0 = (g == 0) ? 0 : (g == 1) ? 43 : 86;
            const int ic1 = (g == 0) ? 43 : (g == 1) ? 86 : 128;

            for (int e = tid; e < 4 * DM; e += 384) {
                int r = e >> 7, d = e & 127;
                int b = b0 + r;
                float a = bval[d] + g_temb[((size_t)b * TOTL + F) * DM + d];
#pragma unroll
                for (int c = 0; c < CIN; c++) a = fmaf(sPred[r][c], g_wvt[c * DM + d], a);
                g_emb[((size_t)b * TOTL + F) * DM + d] = a;
            }
            __syncthreads();

            prolog_stage<3>(b0, F, g_emb, g_wc,             c1b, g_c1, sA4, sRedA, sRedB, tid, o, g, ic0, ic1);
            prolog_stage<5>(b0, F, g_c1,  g_wc + WCONV,     c2b, g_c2, sA4, sRedA, sRedB, tid, o, g, ic0, ic1);
            prolog_stage<7>(b0, F, g_c2,  g_wc + 2 * WCONV, c3b, g_c3, sA4, sRedA, sRedB, tid, o, g, ic0, ic1);

            for (int e = tid; e < 4 * 7 * DM; e += 384) {
                int ic = e & 127, rp = e >> 7;
                int r = rp / 7, p = rp - r * 7;
                sA4[e] = g_c3[((size_t)(b0 + r) * TOTL + F - 6 + p) * DM + ic];
            }
            __syncthreads();
            {
                int rq = tid / 96, cq = tid - rq * 96;
                float acc[7][4];
#pragma unroll
                for (int p = 0; p < 7; p++)
#pragma unroll
                    for (int c = 0; c < 4; c++) acc[p][c] = 0.f;
                const float4* wv = reinterpret_cast<const float4*>(g_wit) + cq;
                const float* xb = sA4 + rq * 7 * DM;
                for (int k = 0; k < DM; k++) {
                    float4 w = wv[(size_t)k * 96];
                    float x[7];
#pragma unroll
                    for (int p = 0; p < 7; p++) x[p] = xb[p * DM + k];
#pragma unroll
                    for (int p = 0; p < 7; p++) {
                        acc[p][0] = fmaf(w.x, x[p], acc[p][0]);
                        acc[p][1] = fmaf(w.y, x[p], acc[p][1]);
                        acc[p][2] = fmaf(w.z, x[p], acc[p][2]);
                        acc[p][3] = fmaf(w.w, x[p], acc[p][3]);
                    }
                }
                float4 bo = reinterpret_cast<const float4*>(gbi)[cq];
#pragma unroll
                for (int p = 0; p < 7; p++) {
                    float4 v;
                    v.x = acc[p][0] + bo.x; v.y = acc[p][1] + bo.y;
                    v.z = acc[p][2] + bo.z; v.w = acc[p][3] + bo.w;
                    *reinterpret_cast<float4*>(
                        g_gx + ((size_t)(b0 + rq) * TOTL + F - 6 + p) * G3 + cq * 4) = v;
                }
            }
            __syncthreads();
        }

        // ---- GRU t-loop (R10-verbatim: gx loaded at loop top, used after chain) ----
        int j = tid;
        ulonglong2 wr[32];
        {
            const ulonglong2* p = reinterpret_cast<const ulonglong2*>(Wh + (size_t)j * DM);
#pragma unroll
            for (int q = 0; q < 32; q++) wr[q] = p[q];
        }
        float bhj = bh[j];

        for (int e = j; e < 4 * DM; e += 384) (&h_s[0][0])[e] = 0.f;
        __syncthreads();

        for (int t = 0; t < SEQL; t++) {
            float gxv[4];
#pragma unroll
            for (int r = 0; r < 4; r++) {
                int b = b0 + r;
                gxv[r] = (t < 6)
                    ? g_lbgx[(((size_t)i * BB + b) * 6 + t) * G3 + j]
                    : g_gx[((size_t)b * TOTL + i + t) * G3 + j];
            }
            unsigned long long c0 = 0, c1 = 0, c2 = 0, c3 = 0;
            const ulonglong2* h0 = reinterpret_cast<const ulonglong2*>(h_s[0]);
            const ulonglong2* h1 = reinterpret_cast<const ulonglong2*>(h_s[1]);
            const ulonglong2* h2 = reinterpret_cast<const ulonglong2*>(h_s[2]);
            const ulonglong2* h3 = reinterpret_cast<const ulonglong2*>(h_s[3]);
#pragma unroll
            for (int q = 0; q < 32; q++) {
                ulonglong2 w  = wr[q];
                ulonglong2 x0 = h0[q], x1 = h1[q], x2 = h2[q], x3 = h3[q];
                ffma2(c0, x0.x, w.x); ffma2(c0, x0.y, w.y);
                ffma2(c1, x1.x, w.x); ffma2(c1, x1.y, w.y);
                ffma2(c2, x2.x, w.x); ffma2(c2, x2.y, w.y);
                ffma2(c3, x3.x, w.x); ffma2(c3, x3.y, w.y);
            }
            float accs[4] = {sum2(c0), sum2(c1), sum2(c2), sum2(c3)};
#pragma unroll
            for (int r = 0; r < 4; r++) {
                float gh = accs[r] + bhj;
                if (j < 2 * DM) S1[r][j] = gxv[r] + gh;
                else            { S1[r][j] = gh; S2[r][j - 2 * DM] = gxv[r]; }
            }
            __syncthreads();
            for (int e = j; e < 4 * DM; e += 384) {
                int r = e >> 7, d = e & 127;
                float rg = __fdividef(1.f, 1.f + __expf(-S1[r][d]));
                float zg = __fdividef(1.f, 1.f + __expf(-S1[r][DM + d]));
                float na = S2[r][d] + rg * S1[r][2 * DM + d];
                float ng = 1.f - __fdividef(2.f, __expf(2.f * na) + 1.f);
                h_s[r][d] = (1.f - zg) * ng + zg * h_s[r][d];
            }
            __syncthreads();
        }

        if (j < 4 * CIN) {
            int r = j / CIN, c = j - r * CIN;
            float acc = fcb[c];
            for (int d = 0; d < DM; d++) acc = fmaf(h_s[r][d], fcw[c * DM + d], acc);
            sPred[r][c] = acc;
            dout[((size_t)(b0 + r) * PREDL + i) * CIN + c] = acc;
        }
    }
}

// ---------------- launcher ----------------
extern "C" void kernel_launch(void* const* d_in, const int* in_sizes, int n_in,
                              void* d_out, int out_size) {
    (void)in_sizes; (void)n_in; (void)out_size;
    const float* x_enc  = (const float*)d_in[0];
    const int*   y_mark = (const int*)  d_in[2];
    const float* hour_e = (const float*)d_in[3];
    const float* wk_e   = (const float*)d_in[4];
    const float* day_e  = (const float*)d_in[5];
    const float* mon_e  = (const float*)d_in[6];
    const float* W_val  = (const float*)d_in[7];
    const float* b_val  = (const float*)d_in[8];
    const float* c1w    = (const float*)d_in[9];
    const float* c1b    = (const float*)d_in[10];
    const float* c2w    = (const float*)d_in[11];
    const float* c2b    = (const float*)d_in[12];
    const float* c3w    = (const float*)d_in[13];
    const float* c3b    = (const float*)d_in[14];
    const float* gWi    = (const float*)d_in[15];
    const float* gWh    = (const float*)d_in[16];
    const float* gbi    = (const float*)d_in[17];
    const float* gbh    = (const float*)d_in[18];
    const float* fcw    = (const float*)d_in[19];
    const float* fcb    = (const float*)d_in[20];
    float* out = (float*)d_out;

    // prep: 2 launches
    prep1_kernel<<<(BB * TOTL * CIN + 255) / 256, 256>>>(c1w, c2w, c3w, W_val, gWi, x_enc);
    prep2_kernel<<<BB * TOTL, DM>>>(y_mark, hour_e, wk_e, day_e, mon_e, b_val);

    // fused upfront: conv stage + paired lb cascade per launch (4 launches)
    stage_kernel<0><<<MAINB + 1536, 256>>>(c1b);           // conv1 main + lb0
    stage_kernel<1><<<MAINB + 3072, 256>>>(c2b);           // conv2 main + lb1
    stage_kernel<2><<<MAINB + 4608, 256>>>(c3b);           // conv3 main + lb2
    stage_kernel<3><<<dim3(MAINB + 4608, 3), 256>>>(gbi);  // gx main + lbgx

    // all 48 autoregressive steps in one persistent kernel
    loop_kernel<<<BB / 4, 384>>>(gWh, gbh, fcw, fcb, b_val, c1b, c2b, c3b, gbi, out);
}